// round 9
// baseline (speedup 1.0000x reference)
#include <cuda_runtime.h>

#define FFT_L   8192
#define NLAYERS 4
#define NSTATE  64
#define NROWS   4096
#define THREADS 512

// ---------------- static device scratch ----------------
__device__ __align__(16) float  g_scratch[(size_t)NROWS * FFT_L];   // ping buffer
__device__ __align__(16) float2 g_tw[FFT_L];                        // W_N^k
__device__ __align__(16) float2 g_kraw[NLAYERS][FFT_L];             // raw K(omega_j)
__device__ __align__(16) float2 g_ke[NLAYERS][FFT_L];               // Hermitian kernel * (1/N)

// ---------------- packed complex (f32x2 in one 64-bit register pair) ----------------
typedef unsigned long long cplx;   // low 32 bits = re, high 32 bits = im (same layout as float2)

__device__ __forceinline__ cplx cpack(float r, float i) {
    cplx v; asm("mov.b64 %0, {%1, %2};" : "=l"(v) : "f"(r), "f"(i)); return v;
}
__device__ __forceinline__ void cunpack(cplx v, float& r, float& i) {
    asm("mov.b64 {%0, %1}, %2;" : "=f"(r), "=f"(i) : "l"(v));
}
__device__ __forceinline__ cplx cadd(cplx a, cplx b) {
    cplx r; asm("add.rn.f32x2 %0, %1, %2;" : "=l"(r) : "l"(a), "l"(b)); return r;
}
__device__ __forceinline__ cplx csub(cplx a, cplx b) {   // a - b = fma(b, -1, a)
    const cplx NEG1 = 0xbf800000bf800000ull;
    cplx r; asm("fma.rn.f32x2 %0, %1, %2, %3;" : "=l"(r) : "l"(b), "l"(NEG1), "l"(a)); return r;
}
template <bool INV>
__device__ __forceinline__ cplx mulj(cplx a) {   // * (-i) fwd, * (+i) inv
    float r, i; cunpack(a, r, i);
    return INV ? cpack(-i, r) : cpack(i, -r);
}
__device__ __forceinline__ cplx cmul(cplx a, cplx b) {   // scalar cross-term form
    float ar, ai, br, bi;
    cunpack(a, ar, ai); cunpack(b, br, bi);
    return cpack(fmaf(ar, br, -ai * bi), fmaf(ar, bi, ai * br));
}
__device__ __forceinline__ cplx conjc(cplx a) {
    float r, i; cunpack(a, r, i);
    return cpack(r, -i);
}
__device__ __forceinline__ float gelu_exact(float v) {
    return 0.5f * v * (1.0f + erff(v * 0.70710678118654752f));
}
// pair-level bank swizzle: P indexes 16B pairs (elements 2P, 2P+1)
__device__ __forceinline__ int swp(int P) { return P ^ ((P >> 3) & 7); }
__device__ __forceinline__ cplx ld_elem(const cplx* s, int i) {
    return s[(swp(i >> 1) << 1) | (i & 1)];
}

// ---------------- DFT-8 / DFT-16 in packed registers ----------------
template <bool INV>
__device__ __forceinline__ void dft8(cplx a[8]) {
    const float CC = 0.70710678118654752f;
    cplx s0 = cadd(a[0], a[4]), s1 = csub(a[0], a[4]);
    cplx s2 = cadd(a[2], a[6]), s3 = mulj<INV>(csub(a[2], a[6]));
    cplx E0 = cadd(s0, s2), E2 = csub(s0, s2);
    cplx E1 = cadd(s1, s3), E3 = csub(s1, s3);
    cplx t0 = cadd(a[1], a[5]), t1 = csub(a[1], a[5]);
    cplx t2 = cadd(a[3], a[7]), t3 = mulj<INV>(csub(a[3], a[7]));
    cplx O0 = cadd(t0, t2), O2 = csub(t0, t2);
    cplx O1 = cadd(t1, t3), O3 = csub(t1, t3);
    float o1x, o1y, o3x, o3y;
    cunpack(O1, o1x, o1y);
    cunpack(O3, o3x, o3y);
    cplx O1w = INV ? cpack(CC * (o1x - o1y), CC * (o1x + o1y))
                   : cpack(CC * (o1x + o1y), CC * (o1y - o1x));
    cplx O2w = mulj<INV>(O2);
    cplx O3w = INV ? cpack(-CC * (o3x + o3y), CC * (o3x - o3y))
                   : cpack(CC * (o3y - o3x), -CC * (o3x + o3y));
    a[0] = cadd(E0, O0);  a[4] = csub(E0, O0);
    a[1] = cadd(E1, O1w); a[5] = csub(E1, O1w);
    a[2] = cadd(E2, O2w); a[6] = csub(E2, O2w);
    a[3] = cadd(E3, O3w); a[7] = csub(E3, O3w);
}

template <bool INV>
__device__ __forceinline__ void dft16(const cplx a[16], cplx X[16]) {
    cplx E[8] = {a[0], a[2], a[4], a[6], a[8], a[10], a[12], a[14]};
    cplx O[8] = {a[1], a[3], a[5], a[7], a[9], a[11], a[13], a[15]};
    dft8<INV>(E);
    dft8<INV>(O);
    const float c1 = 0.9238795325112867f, s1 = 0.3826834323650898f,
                SQ = 0.7071067811865476f;
    const float sg = INV ? 1.0f : -1.0f;
    cplx W[8];
    W[0] = cpack(1.f, 0.f);
    W[1] = cpack(c1, sg * s1);
    W[2] = cpack(SQ, sg * SQ);
    W[3] = cpack(s1, sg * c1);
    W[4] = cpack(0.f, sg);
    W[5] = cpack(-s1, sg * c1);
    W[6] = cpack(-SQ, sg * SQ);
    W[7] = cpack(-c1, sg * s1);
#pragma unroll
    for (int k = 0; k < 8; ++k) {
        cplx t = cmul(O[k], W[k]);
        X[k]     = cadd(E[k], t);
        X[k + 8] = csub(E[k], t);
    }
}

// ---------------- prologue kernels (scalar float math, unchanged) ----------------
__global__ void init_tw_kernel() {
    int j = blockIdx.x * blockDim.x + threadIdx.x;
    if (j < FFT_L) {
        float s, c;
        sincospif(-(float)j / (float)(FFT_L / 2), &s, &c);
        g_tw[j] = make_float2(c, s);
    }
}

__global__ void compute_k_kernel(const float* __restrict__ Lr, const float* __restrict__ Li,
                                 const float* __restrict__ P,  const float* __restrict__ B,
                                 const float* __restrict__ Ct, const float* __restrict__ step) {
    int gid = blockIdx.x * blockDim.x + threadIdx.x;
    if (gid >= NLAYERS * FFT_L) return;
    int layer = gid >> 13;
    int j     = gid & (FFT_L - 1);
    const float* lr = Lr + layer * NSTATE;
    const float* li = Li + layer * NSTATE;
    const float* Pp = P  + layer * NSTATE;
    const float* Bp = B  + layer * NSTATE;
    const float* Cp = Ct + layer * NSTATE;
    float st = step[layer];

    float ang = (-6.2831855f * (float)j) / 8192.0f;
    float s, c;
    sincosf(ang, &s, &c);
    float opr = 1.0f + c, opi = s;
    float omr = 1.0f - c, omi = -s;
    float inv_p2 = 1.0f / (opr * opr + opi * opi);
    float qr = (omr * opr + omi * opi) * inv_p2;
    float qi = (omi * opr - omr * opi) * inv_p2;
    float gsc = 2.0f / st;
    float gr = gsc * qr, gi = gsc * qi;
    float cr = 2.0f * opr * inv_p2, ci = -2.0f * opi * inv_p2;

    float k00r = 0.f, k00i = 0.f, k01r = 0.f, k01i = 0.f;
    float k10r = 0.f, k10i = 0.f, k11r = 0.f, k11i = 0.f;
#pragma unroll 8
    for (int n = 0; n < NSTATE; n++) {
        float dr = gr - lr[n];
        float di = gi - li[n];
        float inv = 1.0f / (dr * dr + di * di);
        float ir = dr * inv, ii = -di * inv;
        float b = Bp[n], p = Pp[n], ct = Cp[n];
        float v00 = ct * b, v01 = ct * p, v10 = p * b, v11 = p * p;
        k00r += v00 * ir; k00i += v00 * ii;
        k01r += v01 * ir; k01i += v01 * ii;
        k10r += v10 * ir; k10i += v10 * ii;
        k11r += v11 * ir; k11i += v11 * ii;
    }
    float d1r = 1.0f + k11r, d1i = k11i;
    float invd1 = 1.0f / (d1r * d1r + d1i * d1i);
    float numr = k01r * k10r - k01i * k10i;
    float numi = k01r * k10i + k01i * k10r;
    float qr2 = (numr * d1r + numi * d1i) * invd1;
    float qi2 = (numi * d1r - numr * d1i) * invd1;
    float tr = k00r - qr2, ti = k00i - qi2;
    g_kraw[layer][j] = make_float2(cr * tr - ci * ti, cr * ti + ci * tr);
}

__global__ void symmetrize_k_kernel() {
    int gid = blockIdx.x * blockDim.x + threadIdx.x;
    if (gid >= NLAYERS * FFT_L) return;
    int layer = gid >> 13;
    int j     = gid & (FFT_L - 1);
    float2 K1 = g_kraw[layer][j];
    float2 K2 = g_kraw[layer][(FFT_L - j) & (FFT_L - 1)];
    const float sc = 0.5f / (float)FFT_L;   // Hermitian part * 1/N
    g_ke[layer][j] = make_float2((K1.x + K2.x) * sc, (K1.y - K2.y) * sc);
}

// ---------------- T=0 twiddle+store (per-butterfly chains), pairs within butterfly ----------------
template <bool INV>
__device__ __forceinline__ void store0(ulonglong2* __restrict__ dst, cplx a[8], cplx b[8], int t) {
    ulonglong2 w01 = *(const ulonglong2*)&g_tw[t << 1];
    cplx wA1 = INV ? conjc(w01.x) : w01.x;
    cplx wB1 = INV ? conjc(w01.y) : w01.y;
    cplx wA2 = cmul(wA1, wA1), wA3 = cmul(wA2, wA1), wA4 = cmul(wA2, wA2);
    cplx wA5 = cmul(wA4, wA1), wA6 = cmul(wA3, wA3), wA7 = cmul(wA4, wA3);
    cplx wB2 = cmul(wB1, wB1), wB3 = cmul(wB2, wB1), wB4 = cmul(wB2, wB2);
    cplx wB5 = cmul(wB4, wB1), wB6 = cmul(wB3, wB3), wB7 = cmul(wB4, wB3);
    int Pb = t << 3;
    dst[swp(Pb + 0)] = make_ulonglong2(a[0],            cmul(a[1], wA1));
    dst[swp(Pb + 1)] = make_ulonglong2(cmul(a[2], wA2), cmul(a[3], wA3));
    dst[swp(Pb + 2)] = make_ulonglong2(cmul(a[4], wA4), cmul(a[5], wA5));
    dst[swp(Pb + 3)] = make_ulonglong2(cmul(a[6], wA6), cmul(a[7], wA7));
    dst[swp(Pb + 4)] = make_ulonglong2(b[0],            cmul(b[1], wB1));
    dst[swp(Pb + 5)] = make_ulonglong2(cmul(b[2], wB2), cmul(b[3], wB3));
    dst[swp(Pb + 6)] = make_ulonglong2(cmul(b[4], wB4), cmul(b[5], wB5));
    dst[swp(Pb + 7)] = make_ulonglong2(cmul(b[6], wB6), cmul(b[7], wB7));
}

// ---------------- generic radix-8 pass for T in {3, 6}: shared twiddle chain ----------------
template <bool INV, int T>
__device__ __forceinline__ void r8_pass(const ulonglong2* __restrict__ src,
                                        ulonglong2* __restrict__ dst) {
    int t = threadIdx.x;
    cplx a[8], b[8];
#pragma unroll
    for (int j = 0; j < 8; ++j) {
        ulonglong2 v = src[swp(t + 512 * j)];
        a[j] = v.x;
        b[j] = v.y;
    }
    dft8<INV>(a);
    dft8<INV>(b);
    int idx = t << 1;
    int pT = idx & ~((1 << T) - 1);
    int qA = idx & ((1 << T) - 1);
    cplx w1 = *(const cplx*)&g_tw[pT];
    if (INV) w1 = conjc(w1);
    cplx w2 = cmul(w1, w1), w3 = cmul(w2, w1), w4 = cmul(w2, w2);
    cplx w5 = cmul(w4, w1), w6 = cmul(w3, w3), w7 = cmul(w4, w3);
    int Pb = (qA >> 1) + (pT << 2);
    const int S = 1 << (T - 1);
    dst[swp(Pb + 0 * S)] = make_ulonglong2(a[0], b[0]);
    dst[swp(Pb + 1 * S)] = make_ulonglong2(cmul(a[1], w1), cmul(b[1], w1));
    dst[swp(Pb + 2 * S)] = make_ulonglong2(cmul(a[2], w2), cmul(b[2], w2));
    dst[swp(Pb + 3 * S)] = make_ulonglong2(cmul(a[3], w3), cmul(b[3], w3));
    dst[swp(Pb + 4 * S)] = make_ulonglong2(cmul(a[4], w4), cmul(b[4], w4));
    dst[swp(Pb + 5 * S)] = make_ulonglong2(cmul(a[5], w5), cmul(b[5], w5));
    dst[swp(Pb + 6 * S)] = make_ulonglong2(cmul(a[6], w6), cmul(b[6], w6));
    dst[swp(Pb + 7 * S)] = make_ulonglong2(cmul(a[7], w7), cmul(b[7], w7));
}

// ---------------- fused per-layer kernel ----------------
__global__ void __launch_bounds__(THREADS, 1)
ssm_layer_kernel(const float* __restrict__ in, float* __restrict__ out, int layer) {
    extern __shared__ ulonglong2 smem4[];
    ulonglong2* X4 = smem4;             // 4096 pairs, swizzled
    ulonglong2* Y4 = smem4 + 4096;      // 4096 pairs, swizzled
    ulonglong2* U4 = smem4 + 8192;      // residual stash, plain pair layout

    size_t row = (size_t)blockIdx.x * 2;
    const float* in0 = in + row * FFT_L;
    const float* in1 = in + (row + 1) * FFT_L;
    int t = threadIdx.x;

    // ---- F1: radix-8 (T=0) from gmem; stash residual pairs ----
    {
        cplx a[8], b[8];
#pragma unroll
        for (int j = 0; j < 8; ++j) {
            int i = (t << 1) + 1024 * j;
            float2 va = *(const float2*)(in0 + i);
            float2 vb = *(const float2*)(in1 + i);
            a[j] = cpack(va.x, vb.x);
            b[j] = cpack(va.y, vb.y);
            U4[t + 512 * j] = make_ulonglong2(a[j], b[j]);
        }
        dft8<false>(a);
        dft8<false>(b);
        store0<false>(X4, a, b, t);
    }
    __syncthreads();

    r8_pass<false, 3>(X4, Y4); __syncthreads();
    r8_pass<false, 6>(Y4, X4); __syncthreads();

    // ---- FUSED: F4 (radix-16) -> filter -> I1 (two inverse radix-8, T=0) in regs ----
    {
        const cplx* Xs = (const cplx*)X4;
        const cplx* __restrict__ ke = (const cplx*)g_ke[layer];
        cplx a[16], S[16];
#pragma unroll
        for (int j = 0; j < 16; ++j) a[j] = ld_elem(Xs, t + (j << 9));
        dft16<false>(a, S);
        // filter: thread t holds spectrum at frequencies t + 512k
#pragma unroll
        for (int k = 0; k < 16; ++k) S[k] = cmul(S[k], ke[t + (k << 9)]);
        // inverse T=0 butterflies idx=t (even k) and idx=t+512 (odd k)
        cplx ai[8], bi[8];
#pragma unroll
        for (int j = 0; j < 8; ++j) {
            ai[j] = S[2 * j];
            bi[j] = S[2 * j + 1];
        }
        dft8<true>(ai);
        dft8<true>(bi);
        // store with conjugate twiddle chains: dst[8*idx + k] *= conj(W^{idx*k})
        cplx wA1 = conjc(*(const cplx*)&g_tw[t]);         // idx = t
        cplx wB1 = conjc(*(const cplx*)&g_tw[t + 512]);   // idx = t + 512
        cplx wA2 = cmul(wA1, wA1), wA3 = cmul(wA2, wA1), wA4 = cmul(wA2, wA2);
        cplx wA5 = cmul(wA4, wA1), wA6 = cmul(wA3, wA3), wA7 = cmul(wA4, wA3);
        cplx wB2 = cmul(wB1, wB1), wB3 = cmul(wB2, wB1), wB4 = cmul(wB2, wB2);
        cplx wB5 = cmul(wB4, wB1), wB6 = cmul(wB3, wB3), wB7 = cmul(wB4, wB3);
        int Pa = t << 2;               // pairs for elements 8t .. 8t+7
        Y4[swp(Pa + 0)] = make_ulonglong2(ai[0],            cmul(ai[1], wA1));
        Y4[swp(Pa + 1)] = make_ulonglong2(cmul(ai[2], wA2), cmul(ai[3], wA3));
        Y4[swp(Pa + 2)] = make_ulonglong2(cmul(ai[4], wA4), cmul(ai[5], wA5));
        Y4[swp(Pa + 3)] = make_ulonglong2(cmul(ai[6], wA6), cmul(ai[7], wA7));
        int Pb = Pa + 2048;            // pairs for elements 8(t+512) .. +7
        Y4[swp(Pb + 0)] = make_ulonglong2(bi[0],            cmul(bi[1], wB1));
        Y4[swp(Pb + 1)] = make_ulonglong2(cmul(bi[2], wB2), cmul(bi[3], wB3));
        Y4[swp(Pb + 2)] = make_ulonglong2(cmul(bi[4], wB4), cmul(bi[5], wB5));
        Y4[swp(Pb + 3)] = make_ulonglong2(cmul(bi[6], wB6), cmul(bi[7], wB7));
    }
    __syncthreads();

    r8_pass<true, 3>(Y4, X4); __syncthreads();
    r8_pass<true, 6>(X4, Y4); __syncthreads();

    // ---- I4: final radix-16 + residual + GELU, straight to gmem ----
    {
        const cplx* Ys = (const cplx*)Y4;
        const cplx* Ue = (const cplx*)U4;   // plain layout: element i at [i]
        float* o0 = out + row * FFT_L;
        float* o1 = out + (row + 1) * FFT_L;
        cplx a[16], Xo[16];
#pragma unroll
        for (int j = 0; j < 16; ++j) a[j] = ld_elem(Ys, t + (j << 9));
        dft16<true>(a, Xo);
#pragma unroll
        for (int k = 0; k < 16; ++k) {
            int i = t + (k << 9);
            cplx s = cadd(Xo[k], Ue[i]);
            float sx, sy;
            cunpack(s, sx, sy);
            o0[i] = gelu_exact(sx);
            o1[i] = gelu_exact(sy);
        }
    }
}

// ---------------- launch ----------------
extern "C" void kernel_launch(void* const* d_in, const int* in_sizes, int n_in,
                              void* d_out, int out_size) {
    const float* u  = (const float*)d_in[0];
    const float* Lr = (const float*)d_in[1];
    const float* Li = (const float*)d_in[2];
    const float* P  = (const float*)d_in[3];
    const float* B  = (const float*)d_in[4];
    const float* Ct = (const float*)d_in[5];
    const float* st = (const float*)d_in[6];
    float* out = (float*)d_out;

    float* scratch = nullptr;
    cudaGetSymbolAddress((void**)&scratch, g_scratch);

    const size_t smem_bytes = 3 * 4096 * sizeof(ulonglong2);   // 192 KB
    cudaFuncSetAttribute(ssm_layer_kernel,
                         cudaFuncAttributeMaxDynamicSharedMemorySize, (int)smem_bytes);

    init_tw_kernel<<<FFT_L / 256, 256>>>();
    compute_k_kernel<<<(NLAYERS * FFT_L) / 256, 256>>>(Lr, Li, P, B, Ct, st);
    symmetrize_k_kernel<<<(NLAYERS * FFT_L) / 256, 256>>>();

    ssm_layer_kernel<<<NROWS / 2, THREADS, smem_bytes>>>(u,       scratch, 0);
    ssm_layer_kernel<<<NROWS / 2, THREADS, smem_bytes>>>(scratch, out,     1);
    ssm_layer_kernel<<<NROWS / 2, THREADS, smem_bytes>>>(out,     scratch, 2);
    ssm_layer_kernel<<<NROWS / 2, THREADS, smem_bytes>>>(scratch, out,     3);
}

// round 10
// speedup vs baseline: 1.2771x; 1.2771x over previous
#include <cuda_runtime.h>

#define FFT_L   8192
#define NLAYERS 4
#define NSTATE  64
#define NROWS   4096
#define THREADS 512

// ---------------- static device tables ----------------
__device__ __align__(16) float2 g_tw[FFT_L];                        // W_N^k
__device__ __align__(16) float2 g_kraw[NLAYERS][FFT_L];             // raw K(omega_j)
__device__ __align__(16) float2 g_ke[NLAYERS][FFT_L];               // Hermitian kernel * (1/N)

// ---------------- complex helpers ----------------
__device__ __forceinline__ float2 cmul(float2 a, float2 b) {
    return make_float2(fmaf(a.x, b.x, -a.y * b.y), fmaf(a.x, b.y, a.y * b.x));
}
__device__ __forceinline__ float2 cadd(float2 a, float2 b) { return make_float2(a.x + b.x, a.y + b.y); }
__device__ __forceinline__ float2 csub(float2 a, float2 b) { return make_float2(a.x - b.x, a.y - b.y); }
template <bool INV>
__device__ __forceinline__ float2 mulj(float2 a) {   // * (-i) fwd, * (+i) inv
    return INV ? make_float2(-a.y, a.x) : make_float2(a.y, -a.x);
}
__device__ __forceinline__ float gelu_exact(float v) {
    return 0.5f * v * (1.0f + erff(v * 0.70710678118654752f));
}
// pair-level bank swizzle: P indexes 16B pairs (elements 2P, 2P+1)
__device__ __forceinline__ int swp(int P) { return P ^ ((P >> 3) & 7); }
__device__ __forceinline__ float2 ld_elem(const float2* s, int i) {
    return s[(swp(i >> 1) << 1) | (i & 1)];
}
__device__ __forceinline__ float4 pack2(float2 a, float2 b) {
    return make_float4(a.x, a.y, b.x, b.y);
}

// ---------------- DFT-8 / DFT-16 in registers ----------------
template <bool INV>
__device__ __forceinline__ void dft8(float2 a[8]) {
    const float CC = 0.70710678118654752f;
    float2 s0 = cadd(a[0], a[4]), s1 = csub(a[0], a[4]);
    float2 s2 = cadd(a[2], a[6]), s3 = mulj<INV>(csub(a[2], a[6]));
    float2 E0 = cadd(s0, s2), E2 = csub(s0, s2);
    float2 E1 = cadd(s1, s3), E3 = csub(s1, s3);
    float2 t0 = cadd(a[1], a[5]), t1 = csub(a[1], a[5]);
    float2 t2 = cadd(a[3], a[7]), t3 = mulj<INV>(csub(a[3], a[7]));
    float2 O0 = cadd(t0, t2), O2 = csub(t0, t2);
    float2 O1 = cadd(t1, t3), O3 = csub(t1, t3);
    float2 O1w = INV ? make_float2(CC * (O1.x - O1.y), CC * (O1.x + O1.y))
                     : make_float2(CC * (O1.x + O1.y), CC * (O1.y - O1.x));
    float2 O2w = mulj<INV>(O2);
    float2 O3w = INV ? make_float2(-CC * (O3.x + O3.y), CC * (O3.x - O3.y))
                     : make_float2(CC * (O3.y - O3.x), -CC * (O3.x + O3.y));
    a[0] = cadd(E0, O0);  a[4] = csub(E0, O0);
    a[1] = cadd(E1, O1w); a[5] = csub(E1, O1w);
    a[2] = cadd(E2, O2w); a[6] = csub(E2, O2w);
    a[3] = cadd(E3, O3w); a[7] = csub(E3, O3w);
}

template <bool INV>
__device__ __forceinline__ void dft16(const float2 a[16], float2 X[16]) {
    float2 E[8] = {a[0], a[2], a[4], a[6], a[8], a[10], a[12], a[14]};
    float2 O[8] = {a[1], a[3], a[5], a[7], a[9], a[11], a[13], a[15]};
    dft8<INV>(E);
    dft8<INV>(O);
    const float c1 = 0.9238795325112867f, s1 = 0.3826834323650898f,
                SQ = 0.7071067811865476f;
    const float sg = INV ? 1.0f : -1.0f;
    float2 W[8];
    W[0] = make_float2(1.f, 0.f);
    W[1] = make_float2(c1, sg * s1);
    W[2] = make_float2(SQ, sg * SQ);
    W[3] = make_float2(s1, sg * c1);
    W[4] = make_float2(0.f, sg);
    W[5] = make_float2(-s1, sg * c1);
    W[6] = make_float2(-SQ, sg * SQ);
    W[7] = make_float2(-c1, sg * s1);
#pragma unroll
    for (int k = 0; k < 8; ++k) {
        float2 t = cmul(O[k], W[k]);
        X[k]     = cadd(E[k], t);
        X[k + 8] = csub(E[k], t);
    }
}

// ---------------- prologue kernels ----------------
__global__ void init_tw_kernel() {
    int j = blockIdx.x * blockDim.x + threadIdx.x;
    if (j < FFT_L) {
        float s, c;
        sincospif(-(float)j / (float)(FFT_L / 2), &s, &c);
        g_tw[j] = make_float2(c, s);
    }
}

__global__ void compute_k_kernel(const float* __restrict__ Lr, const float* __restrict__ Li,
                                 const float* __restrict__ P,  const float* __restrict__ B,
                                 const float* __restrict__ Ct, const float* __restrict__ step) {
    int gid = blockIdx.x * blockDim.x + threadIdx.x;
    if (gid >= NLAYERS * FFT_L) return;
    int layer = gid >> 13;
    int j     = gid & (FFT_L - 1);
    const float* lr = Lr + layer * NSTATE;
    const float* li = Li + layer * NSTATE;
    const float* Pp = P  + layer * NSTATE;
    const float* Bp = B  + layer * NSTATE;
    const float* Cp = Ct + layer * NSTATE;
    float st = step[layer];

    float ang = (-6.2831855f * (float)j) / 8192.0f;
    float s, c;
    sincosf(ang, &s, &c);
    float opr = 1.0f + c, opi = s;
    float omr = 1.0f - c, omi = -s;
    float inv_p2 = 1.0f / (opr * opr + opi * opi);
    float qr = (omr * opr + omi * opi) * inv_p2;
    float qi = (omi * opr - omr * opi) * inv_p2;
    float gsc = 2.0f / st;
    float gr = gsc * qr, gi = gsc * qi;
    float cr = 2.0f * opr * inv_p2, ci = -2.0f * opi * inv_p2;

    float k00r = 0.f, k00i = 0.f, k01r = 0.f, k01i = 0.f;
    float k10r = 0.f, k10i = 0.f, k11r = 0.f, k11i = 0.f;
#pragma unroll 8
    for (int n = 0; n < NSTATE; n++) {
        float dr = gr - lr[n];
        float di = gi - li[n];
        float inv = 1.0f / (dr * dr + di * di);
        float ir = dr * inv, ii = -di * inv;
        float b = Bp[n], p = Pp[n], ct = Cp[n];
        float v00 = ct * b, v01 = ct * p, v10 = p * b, v11 = p * p;
        k00r += v00 * ir; k00i += v00 * ii;
        k01r += v01 * ir; k01i += v01 * ii;
        k10r += v10 * ir; k10i += v10 * ii;
        k11r += v11 * ir; k11i += v11 * ii;
    }
    float d1r = 1.0f + k11r, d1i = k11i;
    float invd1 = 1.0f / (d1r * d1r + d1i * d1i);
    float numr = k01r * k10r - k01i * k10i;
    float numi = k01r * k10i + k01i * k10r;
    float qr2 = (numr * d1r + numi * d1i) * invd1;
    float qi2 = (numi * d1r - numr * d1i) * invd1;
    float tr = k00r - qr2, ti = k00i - qi2;
    g_kraw[layer][j] = make_float2(cr * tr - ci * ti, cr * ti + ci * tr);
}

__global__ void symmetrize_k_kernel() {
    int gid = blockIdx.x * blockDim.x + threadIdx.x;
    if (gid >= NLAYERS * FFT_L) return;
    int layer = gid >> 13;
    int j     = gid & (FFT_L - 1);
    float2 K1 = g_kraw[layer][j];
    float2 K2 = g_kraw[layer][(FFT_L - j) & (FFT_L - 1)];
    const float sc = 0.5f / (float)FFT_L;   // Hermitian part * 1/N
    g_ke[layer][j] = make_float2((K1.x + K2.x) * sc, (K1.y - K2.y) * sc);
}

// ---------------- T=0 twiddle+store (per-butterfly chains), pairs within butterfly ----------------
template <bool INV>
__device__ __forceinline__ void store0(float4* __restrict__ dst, float2 a[8], float2 b[8], int t) {
    float4 w01 = *(const float4*)&g_tw[t << 1];
    float2 wA1 = make_float2(w01.x, INV ? -w01.y : w01.y);
    float2 wB1 = make_float2(w01.z, INV ? -w01.w : w01.w);
    float2 wA2 = cmul(wA1, wA1), wA3 = cmul(wA2, wA1), wA4 = cmul(wA2, wA2);
    float2 wA5 = cmul(wA4, wA1), wA6 = cmul(wA3, wA3), wA7 = cmul(wA4, wA3);
    float2 wB2 = cmul(wB1, wB1), wB3 = cmul(wB2, wB1), wB4 = cmul(wB2, wB2);
    float2 wB5 = cmul(wB4, wB1), wB6 = cmul(wB3, wB3), wB7 = cmul(wB4, wB3);
    int Pb = t << 3;
    dst[swp(Pb + 0)] = pack2(a[0],            cmul(a[1], wA1));
    dst[swp(Pb + 1)] = pack2(cmul(a[2], wA2), cmul(a[3], wA3));
    dst[swp(Pb + 2)] = pack2(cmul(a[4], wA4), cmul(a[5], wA5));
    dst[swp(Pb + 3)] = pack2(cmul(a[6], wA6), cmul(a[7], wA7));
    dst[swp(Pb + 4)] = pack2(b[0],            cmul(b[1], wB1));
    dst[swp(Pb + 5)] = pack2(cmul(b[2], wB2), cmul(b[3], wB3));
    dst[swp(Pb + 6)] = pack2(cmul(b[4], wB4), cmul(b[5], wB5));
    dst[swp(Pb + 7)] = pack2(cmul(b[6], wB6), cmul(b[7], wB7));
}

// ---------------- generic radix-8 pass for T in {3, 6}: shared twiddle chain ----------------
template <bool INV, int T>
__device__ __forceinline__ void r8_pass(const float4* __restrict__ src,
                                        float4* __restrict__ dst) {
    int t = threadIdx.x;
    float2 a[8], b[8];
#pragma unroll
    for (int j = 0; j < 8; ++j) {
        float4 v = src[swp(t + 512 * j)];
        a[j] = make_float2(v.x, v.y);
        b[j] = make_float2(v.z, v.w);
    }
    dft8<INV>(a);
    dft8<INV>(b);
    int idx = t << 1;
    int pT = idx & ~((1 << T) - 1);
    int qA = idx & ((1 << T) - 1);
    float2 w1 = g_tw[pT];
    if (INV) w1.y = -w1.y;
    float2 w2 = cmul(w1, w1), w3 = cmul(w2, w1), w4 = cmul(w2, w2);
    float2 w5 = cmul(w4, w1), w6 = cmul(w3, w3), w7 = cmul(w4, w3);
    int Pb = (qA >> 1) + (pT << 2);
    const int S = 1 << (T - 1);
    dst[swp(Pb + 0 * S)] = pack2(a[0], b[0]);
    dst[swp(Pb + 1 * S)] = pack2(cmul(a[1], w1), cmul(b[1], w1));
    dst[swp(Pb + 2 * S)] = pack2(cmul(a[2], w2), cmul(b[2], w2));
    dst[swp(Pb + 3 * S)] = pack2(cmul(a[3], w3), cmul(b[3], w3));
    dst[swp(Pb + 4 * S)] = pack2(cmul(a[4], w4), cmul(b[4], w4));
    dst[swp(Pb + 5 * S)] = pack2(cmul(a[5], w5), cmul(b[5], w5));
    dst[swp(Pb + 6 * S)] = pack2(cmul(a[6], w6), cmul(b[6], w6));
    dst[swp(Pb + 7 * S)] = pack2(cmul(a[7], w7), cmul(b[7], w7));
}

// ---------------- fused 4-layer block kernel ----------------
__global__ void __launch_bounds__(THREADS, 1)
ssm_block_kernel(const float* __restrict__ in, float* __restrict__ out) {
    extern __shared__ float4 smem4[];
    float4* X4 = smem4;             // 4096 pairs, swizzled
    float4* Y4 = smem4 + 4096;      // 4096 pairs, swizzled
    float4* U4 = smem4 + 8192;      // current layer input (residual), plain pair layout

    size_t row = (size_t)blockIdx.x * 2;
    const float* in0 = in + row * FFT_L;
    const float* in1 = in + (row + 1) * FFT_L;
    float* o0 = out + row * FFT_L;
    float* o1 = out + (row + 1) * FFT_L;
    int t = threadIdx.x;

    for (int layer = 0; layer < NLAYERS; ++layer) {
        // ---- F1: radix-8 (T=0); layer 0 reads gmem (stashing U), others read U ----
        {
            float2 a[8], b[8];
            if (layer == 0) {
#pragma unroll
                for (int j = 0; j < 8; ++j) {
                    int i = (t << 1) + 1024 * j;
                    float2 va = *(const float2*)(in0 + i);
                    float2 vb = *(const float2*)(in1 + i);
                    a[j] = make_float2(va.x, vb.x);
                    b[j] = make_float2(va.y, vb.y);
                    U4[t + 512 * j] = make_float4(va.x, vb.x, va.y, vb.y);
                }
            } else {
#pragma unroll
                for (int j = 0; j < 8; ++j) {
                    float4 v = U4[t + 512 * j];
                    a[j] = make_float2(v.x, v.y);
                    b[j] = make_float2(v.z, v.w);
                }
            }
            dft8<false>(a);
            dft8<false>(b);
            store0<false>(X4, a, b, t);
        }
        __syncthreads();

        r8_pass<false, 3>(X4, Y4); __syncthreads();
        r8_pass<false, 6>(Y4, X4); __syncthreads();

        // ---- FUSED: F4 (radix-16) -> filter -> I1 (two inverse radix-8, T=0) in regs ----
        {
            const float2* Xs = (const float2*)X4;
            const float2* __restrict__ ke = g_ke[layer];
            float2 a[16], S[16];
#pragma unroll
            for (int j = 0; j < 16; ++j) a[j] = ld_elem(Xs, t + (j << 9));
            dft16<false>(a, S);
            // filter: thread t holds spectrum at frequencies t + 512k
#pragma unroll
            for (int k = 0; k < 16; ++k) S[k] = cmul(S[k], ke[t + (k << 9)]);
            // inverse T=0 butterflies idx=t (even k) and idx=t+512 (odd k)
            float2 ai[8], bi[8];
#pragma unroll
            for (int j = 0; j < 8; ++j) {
                ai[j] = S[2 * j];
                bi[j] = S[2 * j + 1];
            }
            dft8<true>(ai);
            dft8<true>(bi);
            // store with conjugate twiddle chains: dst[8*idx + k] *= conj(W^{idx*k})
            float2 wA1 = g_tw[t];       wA1.y = -wA1.y;        // idx = t
            float2 wB1 = g_tw[t + 512]; wB1.y = -wB1.y;        // idx = t + 512
            float2 wA2 = cmul(wA1, wA1), wA3 = cmul(wA2, wA1), wA4 = cmul(wA2, wA2);
            float2 wA5 = cmul(wA4, wA1), wA6 = cmul(wA3, wA3), wA7 = cmul(wA4, wA3);
            float2 wB2 = cmul(wB1, wB1), wB3 = cmul(wB2, wB1), wB4 = cmul(wB2, wB2);
            float2 wB5 = cmul(wB4, wB1), wB6 = cmul(wB3, wB3), wB7 = cmul(wB4, wB3);
            int Pa = t << 2;               // pairs for elements 8t .. 8t+7
            Y4[swp(Pa + 0)] = pack2(ai[0],            cmul(ai[1], wA1));
            Y4[swp(Pa + 1)] = pack2(cmul(ai[2], wA2), cmul(ai[3], wA3));
            Y4[swp(Pa + 2)] = pack2(cmul(ai[4], wA4), cmul(ai[5], wA5));
            Y4[swp(Pa + 3)] = pack2(cmul(ai[6], wA6), cmul(ai[7], wA7));
            int Pb = Pa + 2048;            // pairs for elements 8(t+512) .. +7
            Y4[swp(Pb + 0)] = pack2(bi[0],            cmul(bi[1], wB1));
            Y4[swp(Pb + 1)] = pack2(cmul(bi[2], wB2), cmul(bi[3], wB3));
            Y4[swp(Pb + 2)] = pack2(cmul(bi[4], wB4), cmul(bi[5], wB5));
            Y4[swp(Pb + 3)] = pack2(cmul(bi[6], wB6), cmul(bi[7], wB7));
        }
        __syncthreads();

        r8_pass<true, 3>(Y4, X4); __syncthreads();
        r8_pass<true, 6>(X4, Y4); __syncthreads();

        // ---- I4: final radix-16 + residual + GELU; write U (inner) or gmem (last) ----
        {
            const float2* Ys = (const float2*)Y4;
            float2* Ue = (float2*)U4;   // plain layout: element i at [i]
            float2 a[16], Xo[16];
#pragma unroll
            for (int j = 0; j < 16; ++j) a[j] = ld_elem(Ys, t + (j << 9));
            dft16<true>(a, Xo);
            if (layer == NLAYERS - 1) {
#pragma unroll
                for (int k = 0; k < 16; ++k) {
                    int i = t + (k << 9);
                    float2 u = Ue[i];
                    o0[i] = gelu_exact(Xo[k].x + u.x);
                    o1[i] = gelu_exact(Xo[k].y + u.y);
                }
            } else {
#pragma unroll
                for (int k = 0; k < 16; ++k) {
                    int i = t + (k << 9);
                    float2 u = Ue[i];   // same thread wrote/read element i: no race
                    Ue[i] = make_float2(gelu_exact(Xo[k].x + u.x),
                                        gelu_exact(Xo[k].y + u.y));
                }
            }
        }
        __syncthreads();
    }
}

// ---------------- launch ----------------
extern "C" void kernel_launch(void* const* d_in, const int* in_sizes, int n_in,
                              void* d_out, int out_size) {
    const float* u  = (const float*)d_in[0];
    const float* Lr = (const float*)d_in[1];
    const float* Li = (const float*)d_in[2];
    const float* P  = (const float*)d_in[3];
    const float* B  = (const float*)d_in[4];
    const float* Ct = (const float*)d_in[5];
    const float* st = (const float*)d_in[6];
    float* out = (float*)d_out;

    const size_t smem_bytes = 3 * 4096 * sizeof(float4);   // 192 KB
    cudaFuncSetAttribute(ssm_block_kernel,
                         cudaFuncAttributeMaxDynamicSharedMemorySize, (int)smem_bytes);

    init_tw_kernel<<<FFT_L / 256, 256>>>();
    compute_k_kernel<<<(NLAYERS * FFT_L) / 256, 256>>>(Lr, Li, P, B, Ct, st);
    symmetrize_k_kernel<<<(NLAYERS * FFT_L) / 256, 256>>>();

    ssm_block_kernel<<<NROWS / 2, THREADS, smem_bytes>>>(u, out);
}

// round 11
// speedup vs baseline: 1.2870x; 1.0077x over previous
#include <cuda_runtime.h>

#define FFT_L   8192
#define NLAYERS 4
#define NSTATE  64
#define NROWS   4096
#define THREADS 512

// ---------------- static device tables ----------------
__device__ __align__(16) float2 g_tw[FFT_L];                        // W_N^k
__device__ __align__(16) float2 g_kraw[NLAYERS][FFT_L];             // raw K(omega_j)
__device__ __align__(16) float2 g_ke[NLAYERS][FFT_L];               // Hermitian kernel * (1/N)

// ---------------- complex helpers ----------------
__device__ __forceinline__ float2 cmul(float2 a, float2 b) {
    return make_float2(fmaf(a.x, b.x, -a.y * b.y), fmaf(a.x, b.y, a.y * b.x));
}
__device__ __forceinline__ float2 cadd(float2 a, float2 b) { return make_float2(a.x + b.x, a.y + b.y); }
__device__ __forceinline__ float2 csub(float2 a, float2 b) { return make_float2(a.x - b.x, a.y - b.y); }
template <bool INV>
__device__ __forceinline__ float2 mulj(float2 a) {   // * (-i) fwd, * (+i) inv
    return INV ? make_float2(-a.y, a.x) : make_float2(a.y, -a.x);
}
__device__ __forceinline__ float gelu_exact(float v) {
    return 0.5f * v * (1.0f + erff(v * 0.70710678118654752f));
}
// pair-level bank swizzle: P indexes 16B pairs (elements 2P, 2P+1)
__device__ __forceinline__ int swp(int P) { return P ^ ((P >> 3) & 7); }
__device__ __forceinline__ float2 ld_elem(const float2* s, int i) {
    return s[(swp(i >> 1) << 1) | (i & 1)];
}
__device__ __forceinline__ float4 pack2(float2 a, float2 b) {
    return make_float4(a.x, a.y, b.x, b.y);
}

// ---------------- DFT-8 / DFT-16 in registers ----------------
template <bool INV>
__device__ __forceinline__ void dft8(float2 a[8]) {
    const float CC = 0.70710678118654752f;
    float2 s0 = cadd(a[0], a[4]), s1 = csub(a[0], a[4]);
    float2 s2 = cadd(a[2], a[6]), s3 = mulj<INV>(csub(a[2], a[6]));
    float2 E0 = cadd(s0, s2), E2 = csub(s0, s2);
    float2 E1 = cadd(s1, s3), E3 = csub(s1, s3);
    float2 t0 = cadd(a[1], a[5]), t1 = csub(a[1], a[5]);
    float2 t2 = cadd(a[3], a[7]), t3 = mulj<INV>(csub(a[3], a[7]));
    float2 O0 = cadd(t0, t2), O2 = csub(t0, t2);
    float2 O1 = cadd(t1, t3), O3 = csub(t1, t3);
    float2 O1w = INV ? make_float2(CC * (O1.x - O1.y), CC * (O1.x + O1.y))
                     : make_float2(CC * (O1.x + O1.y), CC * (O1.y - O1.x));
    float2 O2w = mulj<INV>(O2);
    float2 O3w = INV ? make_float2(-CC * (O3.x + O3.y), CC * (O3.x - O3.y))
                     : make_float2(CC * (O3.y - O3.x), -CC * (O3.x + O3.y));
    a[0] = cadd(E0, O0);  a[4] = csub(E0, O0);
    a[1] = cadd(E1, O1w); a[5] = csub(E1, O1w);
    a[2] = cadd(E2, O2w); a[6] = csub(E2, O2w);
    a[3] = cadd(E3, O3w); a[7] = csub(E3, O3w);
}

template <bool INV>
__device__ __forceinline__ void dft16(const float2 a[16], float2 X[16]) {
    float2 E[8] = {a[0], a[2], a[4], a[6], a[8], a[10], a[12], a[14]};
    float2 O[8] = {a[1], a[3], a[5], a[7], a[9], a[11], a[13], a[15]};
    dft8<INV>(E);
    dft8<INV>(O);
    const float c1 = 0.9238795325112867f, s1 = 0.3826834323650898f,
                SQ = 0.7071067811865476f;
    const float sg = INV ? 1.0f : -1.0f;
    float2 W[8];
    W[0] = make_float2(1.f, 0.f);
    W[1] = make_float2(c1, sg * s1);
    W[2] = make_float2(SQ, sg * SQ);
    W[3] = make_float2(s1, sg * c1);
    W[4] = make_float2(0.f, sg);
    W[5] = make_float2(-s1, sg * c1);
    W[6] = make_float2(-SQ, sg * SQ);
    W[7] = make_float2(-c1, sg * s1);
#pragma unroll
    for (int k = 0; k < 8; ++k) {
        float2 t = cmul(O[k], W[k]);
        X[k]     = cadd(E[k], t);
        X[k + 8] = csub(E[k], t);
    }
}

// ---------------- prologue kernels ----------------
__global__ void init_tw_kernel() {
    int j = blockIdx.x * blockDim.x + threadIdx.x;
    if (j < FFT_L) {
        float s, c;
        sincospif(-(float)j / (float)(FFT_L / 2), &s, &c);
        g_tw[j] = make_float2(c, s);
    }
}

__global__ void compute_k_kernel(const float* __restrict__ Lr, const float* __restrict__ Li,
                                 const float* __restrict__ P,  const float* __restrict__ B,
                                 const float* __restrict__ Ct, const float* __restrict__ step) {
    int gid = blockIdx.x * blockDim.x + threadIdx.x;
    if (gid >= NLAYERS * FFT_L) return;
    int layer = gid >> 13;
    int j     = gid & (FFT_L - 1);
    const float* lr = Lr + layer * NSTATE;
    const float* li = Li + layer * NSTATE;
    const float* Pp = P  + layer * NSTATE;
    const float* Bp = B  + layer * NSTATE;
    const float* Cp = Ct + layer * NSTATE;
    float st = step[layer];

    float ang = (-6.2831855f * (float)j) / 8192.0f;
    float s, c;
    sincosf(ang, &s, &c);
    float opr = 1.0f + c, opi = s;
    float omr = 1.0f - c, omi = -s;
    float inv_p2 = 1.0f / (opr * opr + opi * opi);
    float qr = (omr * opr + omi * opi) * inv_p2;
    float qi = (omi * opr - omr * opi) * inv_p2;
    float gsc = 2.0f / st;
    float gr = gsc * qr, gi = gsc * qi;
    float cr = 2.0f * opr * inv_p2, ci = -2.0f * opi * inv_p2;

    float k00r = 0.f, k00i = 0.f, k01r = 0.f, k01i = 0.f;
    float k10r = 0.f, k10i = 0.f, k11r = 0.f, k11i = 0.f;
#pragma unroll 8
    for (int n = 0; n < NSTATE; n++) {
        float dr = gr - lr[n];
        float di = gi - li[n];
        float inv = 1.0f / (dr * dr + di * di);
        float ir = dr * inv, ii = -di * inv;
        float b = Bp[n], p = Pp[n], ct = Cp[n];
        float v00 = ct * b, v01 = ct * p, v10 = p * b, v11 = p * p;
        k00r += v00 * ir; k00i += v00 * ii;
        k01r += v01 * ir; k01i += v01 * ii;
        k10r += v10 * ir; k10i += v10 * ii;
        k11r += v11 * ir; k11i += v11 * ii;
    }
    float d1r = 1.0f + k11r, d1i = k11i;
    float invd1 = 1.0f / (d1r * d1r + d1i * d1i);
    float numr = k01r * k10r - k01i * k10i;
    float numi = k01r * k10i + k01i * k10r;
    float qr2 = (numr * d1r + numi * d1i) * invd1;
    float qi2 = (numi * d1r - numr * d1i) * invd1;
    float tr = k00r - qr2, ti = k00i - qi2;
    g_kraw[layer][j] = make_float2(cr * tr - ci * ti, cr * ti + ci * tr);
}

__global__ void symmetrize_k_kernel() {
    int gid = blockIdx.x * blockDim.x + threadIdx.x;
    if (gid >= NLAYERS * FFT_L) return;
    int layer = gid >> 13;
    int j     = gid & (FFT_L - 1);
    float2 K1 = g_kraw[layer][j];
    float2 K2 = g_kraw[layer][(FFT_L - j) & (FFT_L - 1)];
    const float sc = 0.5f / (float)FFT_L;   // Hermitian part * 1/N
    g_ke[layer][j] = make_float2((K1.x + K2.x) * sc, (K1.y - K2.y) * sc);
}

// ---------------- T=0 twiddle+store (per-butterfly chains), pairs within butterfly ----------------
template <bool INV>
__device__ __forceinline__ void store0(float4* __restrict__ dst, float2 a[8], float2 b[8],
                                       const float2* __restrict__ s_tw, int t) {
    float4 w01 = *(const float4*)&s_tw[t << 1];
    float2 wA1 = make_float2(w01.x, INV ? -w01.y : w01.y);
    float2 wB1 = make_float2(w01.z, INV ? -w01.w : w01.w);
    float2 wA2 = cmul(wA1, wA1), wA3 = cmul(wA2, wA1), wA4 = cmul(wA2, wA2);
    float2 wA5 = cmul(wA4, wA1), wA6 = cmul(wA3, wA3), wA7 = cmul(wA4, wA3);
    float2 wB2 = cmul(wB1, wB1), wB3 = cmul(wB2, wB1), wB4 = cmul(wB2, wB2);
    float2 wB5 = cmul(wB4, wB1), wB6 = cmul(wB3, wB3), wB7 = cmul(wB4, wB3);
    int Pb = t << 3;
    dst[swp(Pb + 0)] = pack2(a[0],            cmul(a[1], wA1));
    dst[swp(Pb + 1)] = pack2(cmul(a[2], wA2), cmul(a[3], wA3));
    dst[swp(Pb + 2)] = pack2(cmul(a[4], wA4), cmul(a[5], wA5));
    dst[swp(Pb + 3)] = pack2(cmul(a[6], wA6), cmul(a[7], wA7));
    dst[swp(Pb + 4)] = pack2(b[0],            cmul(b[1], wB1));
    dst[swp(Pb + 5)] = pack2(cmul(b[2], wB2), cmul(b[3], wB3));
    dst[swp(Pb + 6)] = pack2(cmul(b[4], wB4), cmul(b[5], wB5));
    dst[swp(Pb + 7)] = pack2(cmul(b[6], wB6), cmul(b[7], wB7));
}

// ---------------- generic radix-8 pass for T in {3, 6}: shared twiddle chain ----------------
template <bool INV, int T>
__device__ __forceinline__ void r8_pass(const float4* __restrict__ src,
                                        float4* __restrict__ dst,
                                        const float2* __restrict__ s_tw) {
    int t = threadIdx.x;
    float2 a[8], b[8];
#pragma unroll
    for (int j = 0; j < 8; ++j) {
        float4 v = src[swp(t + 512 * j)];
        a[j] = make_float2(v.x, v.y);
        b[j] = make_float2(v.z, v.w);
    }
    dft8<INV>(a);
    dft8<INV>(b);
    int idx = t << 1;
    int pT = idx & ~((1 << T) - 1);
    int qA = idx & ((1 << T) - 1);
    float2 w1 = s_tw[pT];
    if (INV) w1.y = -w1.y;
    float2 w2 = cmul(w1, w1), w3 = cmul(w2, w1), w4 = cmul(w2, w2);
    float2 w5 = cmul(w4, w1), w6 = cmul(w3, w3), w7 = cmul(w4, w3);
    int Pb = (qA >> 1) + (pT << 2);
    const int S = 1 << (T - 1);
    dst[swp(Pb + 0 * S)] = pack2(a[0], b[0]);
    dst[swp(Pb + 1 * S)] = pack2(cmul(a[1], w1), cmul(b[1], w1));
    dst[swp(Pb + 2 * S)] = pack2(cmul(a[2], w2), cmul(b[2], w2));
    dst[swp(Pb + 3 * S)] = pack2(cmul(a[3], w3), cmul(b[3], w3));
    dst[swp(Pb + 4 * S)] = pack2(cmul(a[4], w4), cmul(b[4], w4));
    dst[swp(Pb + 5 * S)] = pack2(cmul(a[5], w5), cmul(b[5], w5));
    dst[swp(Pb + 6 * S)] = pack2(cmul(a[6], w6), cmul(b[6], w6));
    dst[swp(Pb + 7 * S)] = pack2(cmul(a[7], w7), cmul(b[7], w7));
}

// ---------------- fused 4-layer block kernel ----------------
__global__ void __launch_bounds__(THREADS, 1)
ssm_block_kernel(const float* __restrict__ in, float* __restrict__ out) {
    extern __shared__ float4 smem4[];
    float4* X4 = smem4;             // 4096 pairs, swizzled
    float4* Y4 = smem4 + 4096;      // 4096 pairs, swizzled
    float4* U4 = smem4 + 8192;      // current layer input (residual), plain pair layout
    float2* s_tw = (float2*)(smem4 + 12288);   // 1024-entry twiddle cache (8 KB)

    size_t row = (size_t)blockIdx.x * 2;
    const float* in0 = in + row * FFT_L;
    const float* in1 = in + (row + 1) * FFT_L;
    float* o0 = out + row * FFT_L;
    float* o1 = out + (row + 1) * FFT_L;
    int t = threadIdx.x;

    // cache g_tw[0..1024) in smem: thread t writes entries 2t, 2t+1.
    // F1/store0 of thread t reads exactly those two entries -> no barrier needed
    // before first use; all other stages are behind existing __syncthreads.
    *(float4*)&s_tw[t << 1] = *(const float4*)&g_tw[t << 1];

    for (int layer = 0; layer < NLAYERS; ++layer) {
        // ---- F1: radix-8 (T=0); layer 0 reads gmem (stashing U), others read U ----
        {
            float2 a[8], b[8];
            if (layer == 0) {
#pragma unroll
                for (int j = 0; j < 8; ++j) {
                    int i = (t << 1) + 1024 * j;
                    float2 va = *(const float2*)(in0 + i);
                    float2 vb = *(const float2*)(in1 + i);
                    a[j] = make_float2(va.x, vb.x);
                    b[j] = make_float2(va.y, vb.y);
                    U4[t + 512 * j] = make_float4(va.x, vb.x, va.y, vb.y);
                }
            } else {
#pragma unroll
                for (int j = 0; j < 8; ++j) {
                    float4 v = U4[t + 512 * j];
                    a[j] = make_float2(v.x, v.y);
                    b[j] = make_float2(v.z, v.w);
                }
            }
            dft8<false>(a);
            dft8<false>(b);
            store0<false>(X4, a, b, s_tw, t);
        }
        __syncthreads();

        r8_pass<false, 3>(X4, Y4, s_tw); __syncthreads();
        r8_pass<false, 6>(Y4, X4, s_tw); __syncthreads();

        // ---- FUSED: F4 (radix-16) -> filter -> I1 (two inverse radix-8, T=0) in regs ----
        {
            const float2* Xs = (const float2*)X4;
            const float2* __restrict__ ke = g_ke[layer];
            float2 a[16], S[16];
#pragma unroll
            for (int j = 0; j < 16; ++j) a[j] = ld_elem(Xs, t + (j << 9));
            dft16<false>(a, S);
            // filter: thread t holds spectrum at frequencies t + 512k
#pragma unroll
            for (int k = 0; k < 16; ++k) S[k] = cmul(S[k], ke[t + (k << 9)]);
            // inverse T=0 butterflies idx=t (even k) and idx=t+512 (odd k)
            float2 ai[8], bi[8];
#pragma unroll
            for (int j = 0; j < 8; ++j) {
                ai[j] = S[2 * j];
                bi[j] = S[2 * j + 1];
            }
            dft8<true>(ai);
            dft8<true>(bi);
            // store with conjugate twiddle chains: dst[8*idx + k] *= conj(W^{idx*k})
            float2 wA1 = s_tw[t];       wA1.y = -wA1.y;        // idx = t
            float2 wB1 = s_tw[t + 512]; wB1.y = -wB1.y;        // idx = t + 512
            float2 wA2 = cmul(wA1, wA1), wA3 = cmul(wA2, wA1), wA4 = cmul(wA2, wA2);
            float2 wA5 = cmul(wA4, wA1), wA6 = cmul(wA3, wA3), wA7 = cmul(wA4, wA3);
            float2 wB2 = cmul(wB1, wB1), wB3 = cmul(wB2, wB1), wB4 = cmul(wB2, wB2);
            float2 wB5 = cmul(wB4, wB1), wB6 = cmul(wB3, wB3), wB7 = cmul(wB4, wB3);
            int Pa = t << 2;               // pairs for elements 8t .. 8t+7
            Y4[swp(Pa + 0)] = pack2(ai[0],            cmul(ai[1], wA1));
            Y4[swp(Pa + 1)] = pack2(cmul(ai[2], wA2), cmul(ai[3], wA3));
            Y4[swp(Pa + 2)] = pack2(cmul(ai[4], wA4), cmul(ai[5], wA5));
            Y4[swp(Pa + 3)] = pack2(cmul(ai[6], wA6), cmul(ai[7], wA7));
            int Pb = Pa + 2048;            // pairs for elements 8(t+512) .. +7
            Y4[swp(Pb + 0)] = pack2(bi[0],            cmul(bi[1], wB1));
            Y4[swp(Pb + 1)] = pack2(cmul(bi[2], wB2), cmul(bi[3], wB3));
            Y4[swp(Pb + 2)] = pack2(cmul(bi[4], wB4), cmul(bi[5], wB5));
            Y4[swp(Pb + 3)] = pack2(cmul(bi[6], wB6), cmul(bi[7], wB7));
        }
        __syncthreads();

        r8_pass<true, 3>(Y4, X4, s_tw); __syncthreads();
        r8_pass<true, 6>(X4, Y4, s_tw); __syncthreads();

        // ---- I4: final radix-16 + residual + GELU; write U (inner) or gmem (last) ----
        {
            const float2* Ys = (const float2*)Y4;
            float2* Ue = (float2*)U4;   // plain layout: element i at [i]
            float2 a[16], Xo[16];
#pragma unroll
            for (int j = 0; j < 16; ++j) a[j] = ld_elem(Ys, t + (j << 9));
            dft16<true>(a, Xo);
            if (layer == NLAYERS - 1) {
#pragma unroll
                for (int k = 0; k < 16; ++k) {
                    int i = t + (k << 9);
                    float2 u = Ue[i];
                    o0[i] = gelu_exact(Xo[k].x + u.x);
                    o1[i] = gelu_exact(Xo[k].y + u.y);
                }
            } else {
#pragma unroll
                for (int k = 0; k < 16; ++k) {
                    int i = t + (k << 9);
                    float2 u = Ue[i];   // same thread wrote/read element i: no race
                    Ue[i] = make_float2(gelu_exact(Xo[k].x + u.x),
                                        gelu_exact(Xo[k].y + u.y));
                }
            }
        }
        __syncthreads();
    }
}

// ---------------- launch ----------------
extern "C" void kernel_launch(void* const* d_in, const int* in_sizes, int n_in,
                              void* d_out, int out_size) {
    const float* u  = (const float*)d_in[0];
    const float* Lr = (const float*)d_in[1];
    const float* Li = (const float*)d_in[2];
    const float* P  = (const float*)d_in[3];
    const float* B  = (const float*)d_in[4];
    const float* Ct = (const float*)d_in[5];
    const float* st = (const float*)d_in[6];
    float* out = (float*)d_out;

    const size_t smem_bytes = 3 * 4096 * sizeof(float4) + 1024 * sizeof(float2);   // 200 KB
    cudaFuncSetAttribute(ssm_block_kernel,
                         cudaFuncAttributeMaxDynamicSharedMemorySize, (int)smem_bytes);

    init_tw_kernel<<<FFT_L / 256, 256>>>();
    compute_k_kernel<<<(NLAYERS * FFT_L) / 256, 256>>>(Lr, Li, P, B, Ct, st);
    symmetrize_k_kernel<<<(NLAYERS * FFT_L) / 256, 256>>>();

    ssm_block_kernel<<<NROWS / 2, THREADS, smem_bytes>>>(u, out);
}

// round 12
// speedup vs baseline: 1.3560x; 1.0536x over previous
#include <cuda_runtime.h>

#define FFT_L   8192
#define NLAYERS 4
#define NSTATE  64
#define NROWS   4096
#define THREADS 512

// ---------------- static device tables ----------------
__device__ __align__(16) float2 g_tw[FFT_L];                        // W_N^k
__device__ __align__(16) float2 g_kraw[NLAYERS][FFT_L];             // raw K(omega_j)
__device__ __align__(16) float2 g_ke[NLAYERS][FFT_L];               // Hermitian kernel * (1/N)

// ---------------- complex helpers ----------------
__device__ __forceinline__ float2 cmul(float2 a, float2 b) {
    return make_float2(fmaf(a.x, b.x, -a.y * b.y), fmaf(a.x, b.y, a.y * b.x));
}
__device__ __forceinline__ float2 cadd(float2 a, float2 b) { return make_float2(a.x + b.x, a.y + b.y); }
__device__ __forceinline__ float2 csub(float2 a, float2 b) { return make_float2(a.x - b.x, a.y - b.y); }
template <bool INV>
__device__ __forceinline__ float2 mulj(float2 a) {   // * (-i) fwd, * (+i) inv
    return INV ? make_float2(-a.y, a.x) : make_float2(a.y, -a.x);
}
__device__ __forceinline__ float gelu_exact(float v) {
    return 0.5f * v * (1.0f + erff(v * 0.70710678118654752f));
}
// pair-level bank swizzle: P indexes 16B pairs (elements 2P, 2P+1)
__device__ __forceinline__ int swp(int P) { return P ^ ((P >> 3) & 7); }
__device__ __forceinline__ float2 ld_elem(const float2* s, int i) {
    return s[(swp(i >> 1) << 1) | (i & 1)];
}
__device__ __forceinline__ float4 pack2(float2 a, float2 b) {
    return make_float4(a.x, a.y, b.x, b.y);
}

// Chebyshev twiddle chain: w[k] = W^{k+1}, built via W^{k+1} = 2cos(th)*W^k - W^{k-1}
__device__ __forceinline__ void chain7(float2 w1, float2 w[7]) {
    float twoc = 2.0f * w1.x;
    w[0] = w1;
    w[1] = make_float2(fmaf(twoc, w1.x, -1.0f), twoc * w1.y);
#pragma unroll
    for (int k = 2; k < 7; ++k)
        w[k] = make_float2(fmaf(twoc, w[k - 1].x, -w[k - 2].x),
                           fmaf(twoc, w[k - 1].y, -w[k - 2].y));
}

// ---------------- DFT-8 / DFT-16 in registers ----------------
template <bool INV>
__device__ __forceinline__ void dft8(float2 a[8]) {
    const float CC = 0.70710678118654752f;
    float2 s0 = cadd(a[0], a[4]), s1 = csub(a[0], a[4]);
    float2 s2 = cadd(a[2], a[6]), s3 = mulj<INV>(csub(a[2], a[6]));
    float2 E0 = cadd(s0, s2), E2 = csub(s0, s2);
    float2 E1 = cadd(s1, s3), E3 = csub(s1, s3);
    float2 t0 = cadd(a[1], a[5]), t1 = csub(a[1], a[5]);
    float2 t2 = cadd(a[3], a[7]), t3 = mulj<INV>(csub(a[3], a[7]));
    float2 O0 = cadd(t0, t2), O2 = csub(t0, t2);
    float2 O1 = cadd(t1, t3), O3 = csub(t1, t3);
    float2 O1w = INV ? make_float2(CC * (O1.x - O1.y), CC * (O1.x + O1.y))
                     : make_float2(CC * (O1.x + O1.y), CC * (O1.y - O1.x));
    float2 O2w = mulj<INV>(O2);
    float2 O3w = INV ? make_float2(-CC * (O3.x + O3.y), CC * (O3.x - O3.y))
                     : make_float2(CC * (O3.y - O3.x), -CC * (O3.x + O3.y));
    a[0] = cadd(E0, O0);  a[4] = csub(E0, O0);
    a[1] = cadd(E1, O1w); a[5] = csub(E1, O1w);
    a[2] = cadd(E2, O2w); a[6] = csub(E2, O2w);
    a[3] = cadd(E3, O3w); a[7] = csub(E3, O3w);
}

template <bool INV>
__device__ __forceinline__ void dft16(const float2 a[16], float2 X[16]) {
    float2 E[8] = {a[0], a[2], a[4], a[6], a[8], a[10], a[12], a[14]};
    float2 O[8] = {a[1], a[3], a[5], a[7], a[9], a[11], a[13], a[15]};
    dft8<INV>(E);
    dft8<INV>(O);
    const float c1 = 0.9238795325112867f, s1 = 0.3826834323650898f,
                SQ = 0.7071067811865476f;
    const float sg = INV ? 1.0f : -1.0f;
    float2 W[8];
    W[0] = make_float2(1.f, 0.f);
    W[1] = make_float2(c1, sg * s1);
    W[2] = make_float2(SQ, sg * SQ);
    W[3] = make_float2(s1, sg * c1);
    W[4] = make_float2(0.f, sg);
    W[5] = make_float2(-s1, sg * c1);
    W[6] = make_float2(-SQ, sg * SQ);
    W[7] = make_float2(-c1, sg * s1);
#pragma unroll
    for (int k = 0; k < 8; ++k) {
        float2 t = cmul(O[k], W[k]);
        X[k]     = cadd(E[k], t);
        X[k + 8] = csub(E[k], t);
    }
}

// ---------------- prologue kernels ----------------
__global__ void init_tw_kernel() {
    int j = blockIdx.x * blockDim.x + threadIdx.x;
    if (j < FFT_L) {
        float s, c;
        sincospif(-(float)j / (float)(FFT_L / 2), &s, &c);
        g_tw[j] = make_float2(c, s);
    }
}

__global__ void compute_k_kernel(const float* __restrict__ Lr, const float* __restrict__ Li,
                                 const float* __restrict__ P,  const float* __restrict__ B,
                                 const float* __restrict__ Ct, const float* __restrict__ step) {
    int gid = blockIdx.x * blockDim.x + threadIdx.x;
    if (gid >= NLAYERS * FFT_L) return;
    int layer = gid >> 13;
    int j     = gid & (FFT_L - 1);
    const float* lr = Lr + layer * NSTATE;
    const float* li = Li + layer * NSTATE;
    const float* Pp = P  + layer * NSTATE;
    const float* Bp = B  + layer * NSTATE;
    const float* Cp = Ct + layer * NSTATE;
    float st = step[layer];

    float ang = (-6.2831855f * (float)j) / 8192.0f;
    float s, c;
    sincosf(ang, &s, &c);
    float opr = 1.0f + c, opi = s;
    float omr = 1.0f - c, omi = -s;
    float inv_p2 = 1.0f / (opr * opr + opi * opi);
    float qr = (omr * opr + omi * opi) * inv_p2;
    float qi = (omi * opr - omr * opi) * inv_p2;
    float gsc = 2.0f / st;
    float gr = gsc * qr, gi = gsc * qi;
    float cr = 2.0f * opr * inv_p2, ci = -2.0f * opi * inv_p2;

    float k00r = 0.f, k00i = 0.f, k01r = 0.f, k01i = 0.f;
    float k10r = 0.f, k10i = 0.f, k11r = 0.f, k11i = 0.f;
#pragma unroll 8
    for (int n = 0; n < NSTATE; n++) {
        float dr = gr - lr[n];
        float di = gi - li[n];
        float inv = 1.0f / (dr * dr + di * di);
        float ir = dr * inv, ii = -di * inv;
        float b = Bp[n], p = Pp[n], ct = Cp[n];
        float v00 = ct * b, v01 = ct * p, v10 = p * b, v11 = p * p;
        k00r += v00 * ir; k00i += v00 * ii;
        k01r += v01 * ir; k01i += v01 * ii;
        k10r += v10 * ir; k10i += v10 * ii;
        k11r += v11 * ir; k11i += v11 * ii;
    }
    float d1r = 1.0f + k11r, d1i = k11i;
    float invd1 = 1.0f / (d1r * d1r + d1i * d1i);
    float numr = k01r * k10r - k01i * k10i;
    float numi = k01r * k10i + k01i * k10r;
    float qr2 = (numr * d1r + numi * d1i) * invd1;
    float qi2 = (numi * d1r - numr * d1i) * invd1;
    float tr = k00r - qr2, ti = k00i - qi2;
    g_kraw[layer][j] = make_float2(cr * tr - ci * ti, cr * ti + ci * tr);
}

__global__ void symmetrize_k_kernel() {
    int gid = blockIdx.x * blockDim.x + threadIdx.x;
    if (gid >= NLAYERS * FFT_L) return;
    int layer = gid >> 13;
    int j     = gid & (FFT_L - 1);
    float2 K1 = g_kraw[layer][j];
    float2 K2 = g_kraw[layer][(FFT_L - j) & (FFT_L - 1)];
    const float sc = 0.5f / (float)FFT_L;   // Hermitian part * 1/N
    g_ke[layer][j] = make_float2((K1.x + K2.x) * sc, (K1.y - K2.y) * sc);
}

// ---------------- T=0 twiddle+store for layer-0 F1 (butterflies 2t, 2t+1) ----------------
__device__ __forceinline__ void store0_fwd(float4* __restrict__ dst, float2 a[8], float2 b[8],
                                           const float2* __restrict__ s_tw, int t) {
    float4 w01 = *(const float4*)&s_tw[t << 1];
    float2 wA[7], wB[7];
    chain7(make_float2(w01.x, w01.y), wA);
    chain7(make_float2(w01.z, w01.w), wB);
    int Pb = t << 3;
    dst[swp(Pb + 0)] = pack2(a[0],              cmul(a[1], wA[0]));
    dst[swp(Pb + 1)] = pack2(cmul(a[2], wA[1]), cmul(a[3], wA[2]));
    dst[swp(Pb + 2)] = pack2(cmul(a[4], wA[3]), cmul(a[5], wA[4]));
    dst[swp(Pb + 3)] = pack2(cmul(a[6], wA[5]), cmul(a[7], wA[6]));
    dst[swp(Pb + 4)] = pack2(b[0],              cmul(b[1], wB[0]));
    dst[swp(Pb + 5)] = pack2(cmul(b[2], wB[1]), cmul(b[3], wB[2]));
    dst[swp(Pb + 6)] = pack2(cmul(b[4], wB[3]), cmul(b[5], wB[4]));
    dst[swp(Pb + 7)] = pack2(cmul(b[6], wB[5]), cmul(b[7], wB[6]));
}

// ---------------- T=0 dual-butterfly store (butterflies t and t+512) ----------------
template <bool INV>
__device__ __forceinline__ void dual_bfly_store(float4* __restrict__ dst,
                                                float2 ai[8], float2 bi[8],
                                                const float2* __restrict__ s_tw, int t) {
    float2 w1a = s_tw[t], w1b = s_tw[t + 512];
    if (INV) { w1a.y = -w1a.y; w1b.y = -w1b.y; }
    float2 wA[7], wB[7];
    chain7(w1a, wA);
    chain7(w1b, wB);
    int Pa = t << 2;               // pairs for elements 8t .. 8t+7
    dst[swp(Pa + 0)] = pack2(ai[0],              cmul(ai[1], wA[0]));
    dst[swp(Pa + 1)] = pack2(cmul(ai[2], wA[1]), cmul(ai[3], wA[2]));
    dst[swp(Pa + 2)] = pack2(cmul(ai[4], wA[3]), cmul(ai[5], wA[4]));
    dst[swp(Pa + 3)] = pack2(cmul(ai[6], wA[5]), cmul(ai[7], wA[6]));
    int Pb = Pa + 2048;            // pairs for elements 8(t+512) .. +7
    dst[swp(Pb + 0)] = pack2(bi[0],              cmul(bi[1], wB[0]));
    dst[swp(Pb + 1)] = pack2(cmul(bi[2], wB[1]), cmul(bi[3], wB[2]));
    dst[swp(Pb + 2)] = pack2(cmul(bi[4], wB[3]), cmul(bi[5], wB[4]));
    dst[swp(Pb + 3)] = pack2(cmul(bi[6], wB[5]), cmul(bi[7], wB[6]));
}

// ---------------- generic radix-8 pass for T in {3, 6}: shared twiddle chain ----------------
template <bool INV, int T>
__device__ __forceinline__ void r8_pass(const float4* __restrict__ src,
                                        float4* __restrict__ dst,
                                        const float2* __restrict__ s_tw) {
    int t = threadIdx.x;
    float2 a[8], b[8];
#pragma unroll
    for (int j = 0; j < 8; ++j) {
        float4 v = src[swp(t + 512 * j)];
        a[j] = make_float2(v.x, v.y);
        b[j] = make_float2(v.z, v.w);
    }
    dft8<INV>(a);
    dft8<INV>(b);
    int idx = t << 1;
    int pT = idx & ~((1 << T) - 1);
    int qA = idx & ((1 << T) - 1);
    float2 w1 = s_tw[pT];
    if (INV) w1.y = -w1.y;
    float2 w[7];
    chain7(w1, w);
    int Pb = (qA >> 1) + (pT << 2);
    const int S = 1 << (T - 1);
    dst[swp(Pb + 0 * S)] = pack2(a[0], b[0]);
    dst[swp(Pb + 1 * S)] = pack2(cmul(a[1], w[0]), cmul(b[1], w[0]));
    dst[swp(Pb + 2 * S)] = pack2(cmul(a[2], w[1]), cmul(b[2], w[1]));
    dst[swp(Pb + 3 * S)] = pack2(cmul(a[3], w[2]), cmul(b[3], w[2]));
    dst[swp(Pb + 4 * S)] = pack2(cmul(a[4], w[3]), cmul(b[4], w[3]));
    dst[swp(Pb + 5 * S)] = pack2(cmul(a[5], w[4]), cmul(b[5], w[4]));
    dst[swp(Pb + 6 * S)] = pack2(cmul(a[6], w[5]), cmul(b[6], w[5]));
    dst[swp(Pb + 7 * S)] = pack2(cmul(a[7], w[6]), cmul(b[7], w[6]));
}

// ---------------- fused 4-layer block kernel ----------------
__global__ void __launch_bounds__(THREADS, 1)
ssm_block_kernel(const float* __restrict__ in, float* __restrict__ out) {
    extern __shared__ float4 smem4[];
    float4* X4 = smem4;             // 4096 pairs, swizzled
    float4* Y4 = smem4 + 4096;      // 4096 pairs, swizzled
    float4* U4 = smem4 + 8192;      // current layer input (residual), plain pair layout
    float2* s_tw = (float2*)(smem4 + 12288);   // 1024-entry twiddle cache (8 KB)

    size_t row = (size_t)blockIdx.x * 2;
    const float* in0 = in + row * FFT_L;
    const float* in1 = in + (row + 1) * FFT_L;
    float* o0 = out + row * FFT_L;
    float* o1 = out + (row + 1) * FFT_L;
    int t = threadIdx.x;

    // cache g_tw[0..1024) in smem: thread t writes entries 2t, 2t+1.
    // F1/store0_fwd of thread t reads exactly those two entries -> safe before barrier.
    *(float4*)&s_tw[t << 1] = *(const float4*)&g_tw[t << 1];

    // ---- layer-0 F1: radix-8 (T=0) from gmem; stash residual pairs in U ----
    {
        float2 a[8], b[8];
#pragma unroll
        for (int j = 0; j < 8; ++j) {
            int i = (t << 1) + 1024 * j;
            float2 va = *(const float2*)(in0 + i);
            float2 vb = *(const float2*)(in1 + i);
            a[j] = make_float2(va.x, vb.x);
            b[j] = make_float2(va.y, vb.y);
            U4[t + 512 * j] = make_float4(va.x, vb.x, va.y, vb.y);
        }
        dft8<false>(a);
        dft8<false>(b);
        store0_fwd(X4, a, b, s_tw, t);
    }
    __syncthreads();

    for (int layer = 0; layer < NLAYERS; ++layer) {
        r8_pass<false, 3>(X4, Y4, s_tw); __syncthreads();
        r8_pass<false, 6>(Y4, X4, s_tw); __syncthreads();

        // ---- MID: F4 (radix-16) -> filter -> I1 (two inverse radix-8, T=0), X -> Y ----
        {
            const float2* Xs = (const float2*)X4;
            const float2* __restrict__ ke = g_ke[layer];
            float2 a[16], S[16];
#pragma unroll
            for (int j = 0; j < 16; ++j) a[j] = ld_elem(Xs, t + (j << 9));
            dft16<false>(a, S);
#pragma unroll
            for (int k = 0; k < 16; ++k) S[k] = cmul(S[k], ke[t + (k << 9)]);
            float2 ai[8], bi[8];
#pragma unroll
            for (int j = 0; j < 8; ++j) {
                ai[j] = S[2 * j];
                bi[j] = S[2 * j + 1];
            }
            dft8<true>(ai);
            dft8<true>(bi);
            dual_bfly_store<true>(Y4, ai, bi, s_tw, t);
        }
        __syncthreads();

        r8_pass<true, 3>(Y4, X4, s_tw); __syncthreads();
        r8_pass<true, 6>(X4, Y4, s_tw); __syncthreads();

        if (layer < NLAYERS - 1) {
            // ---- BOUNDARY: I4 (radix-16 inv) + residual/GELU (U r/w) + next F1, Y -> X ----
            const float2* Ys = (const float2*)Y4;
            float2* Ue = (float2*)U4;
            float2 a[16], Xo[16];
#pragma unroll
            for (int j = 0; j < 16; ++j) a[j] = ld_elem(Ys, t + (j << 9));
            dft16<true>(a, Xo);
            float2 v[16];
#pragma unroll
            for (int k = 0; k < 16; ++k) {
                int i = t + (k << 9);
                float2 u = Ue[i];                    // same thread wrote element i
                v[k] = make_float2(gelu_exact(Xo[k].x + u.x),
                                   gelu_exact(Xo[k].y + u.y));
                Ue[i] = v[k];                        // next layer's residual
            }
            // forward T=0 butterflies idx=t (even k) and idx=t+512 (odd k)
            float2 ai[8], bi[8];
#pragma unroll
            for (int j = 0; j < 8; ++j) {
                ai[j] = v[2 * j];
                bi[j] = v[2 * j + 1];
            }
            dft8<false>(ai);
            dft8<false>(bi);
            dual_bfly_store<false>(X4, ai, bi, s_tw, t);
            __syncthreads();
        } else {
            // ---- final I4: radix-16 inv + residual + GELU -> gmem ----
            const float2* Ys = (const float2*)Y4;
            const float2* Ue = (const float2*)U4;
            float2 a[16], Xo[16];
#pragma unroll
            for (int j = 0; j < 16; ++j) a[j] = ld_elem(Ys, t + (j << 9));
            dft16<true>(a, Xo);
#pragma unroll
            for (int k = 0; k < 16; ++k) {
                int i = t + (k << 9);
                float2 u = Ue[i];
                o0[i] = gelu_exact(Xo[k].x + u.x);
                o1[i] = gelu_exact(Xo[k].y + u.y);
            }
        }
    }
}

// ---------------- launch ----------------
extern "C" void kernel_launch(void* const* d_in, const int* in_sizes, int n_in,
                              void* d_out, int out_size) {
    const float* u  = (const float*)d_in[0];
    const float* Lr = (const float*)d_in[1];
    const float* Li = (const float*)d_in[2];
    const float* P  = (const float*)d_in[3];
    const float* B  = (const float*)d_in[4];
    const float* Ct = (const float*)d_in[5];
    const float* st = (const float*)d_in[6];
    float* out = (float*)d_out;

    const size_t smem_bytes = 3 * 4096 * sizeof(float4) + 1024 * sizeof(float2);   // 200 KB
    cudaFuncSetAttribute(ssm_block_kernel,
                         cudaFuncAttributeMaxDynamicSharedMemorySize, (int)smem_bytes);

    init_tw_kernel<<<FFT_L / 256, 256>>>();
    compute_k_kernel<<<(NLAYERS * FFT_L) / 256, 256>>>(Lr, Li, P, B, Ct, st);
    symmetrize_k_kernel<<<(NLAYERS * FFT_L) / 256, 256>>>();

    ssm_block_kernel<<<NROWS / 2, THREADS, smem_bytes>>>(u, out);
}